// round 7
// baseline (speedup 1.0000x reference)
#include <cuda_runtime.h>
#include <math.h>
#include <stdint.h>

#define AA 3072   // A = BS * IA
#define DD 2048   // D = BS * (IA-1)
#define NB 1024   // BS

// scratch ping-pong buffers (no device allocation allowed)
__device__ float g_buf0[AA];
__device__ float g_buf1[AA];

__device__ __forceinline__ uint64_t mk_evict_last_policy() {
    uint64_t pol;
    asm("createpolicy.fractional.L2::evict_last.b64 %0, 1.0;" : "=l"(pol));
    return pol;
}

// EVICT: 0 = streaming (evict-first), 1 = persistent (L2 evict_last via policy)
template<int EVICT>
__device__ __forceinline__ float4 ldW(const float4* p, uint64_t pol) {
    if (EVICT == 1) {
        float4 r;
        asm("ld.global.L2::cache_hint.v4.f32 {%0,%1,%2,%3}, [%4], %5;"
            : "=f"(r.x), "=f"(r.y), "=f"(r.z), "=f"(r.w)
            : "l"(p), "l"(pol));
        return r;
    }
    return __ldcs(p);
}

// ---------------------------------------------------------------------------
// GEMV, warp-per-row, deep explicit load pipeline (8 LDG.128 in flight,
// double-buffered). ACT: 0 none, 1 tanh, 2 tanhshrink.
// ---------------------------------------------------------------------------
template<int ACT, int COLS, int EVICT>
__global__ void __launch_bounds__(256, 2)
gemv_ws(const float* __restrict__ W, const float* __restrict__ x,
        const float* __restrict__ b, float* __restrict__ y)
{
    constexpr int F4       = COLS / 4;     // 768 or 512 float4 per row
    constexpr int PER_LANE = F4 / 32;      // 24 or 16
    constexpr int NBATCH   = PER_LANE / 8; // 3 or 2

    __shared__ float sx[COLS];

    const int lane = threadIdx.x & 31;
    const int warp = threadIdx.x >> 5;
    const int row  = blockIdx.x * 8 + warp;

    const uint64_t pol = (EVICT == 1) ? mk_evict_last_policy() : 0ull;

    const float4* __restrict__ W4 =
        reinterpret_cast<const float4*>(W + (size_t)row * COLS);

    // stage x into shared
    const float4* __restrict__ xg4 = reinterpret_cast<const float4*>(x);
    float4* sx4 = reinterpret_cast<float4*>(sx);
    #pragma unroll
    for (int k = 0; k < F4 / 256; ++k)
        sx4[threadIdx.x + 256 * k] = xg4[threadIdx.x + 256 * k];

    // prologue: batch 0 of W issued BEFORE the barrier
    float4 buf[2][8];
    #pragma unroll
    for (int t = 0; t < 8; ++t)
        buf[0][t] = ldW<EVICT>(&W4[lane + 32 * t], pol);

    __syncthreads();

    float a0 = 0.f, a1 = 0.f, a2 = 0.f, a3 = 0.f;
    #pragma unroll
    for (int bt = 0; bt < NBATCH; ++bt) {
        const int cur = bt & 1;
        if (bt + 1 < NBATCH) {
            #pragma unroll
            for (int t = 0; t < 8; ++t)
                buf[cur ^ 1][t] = ldW<EVICT>(&W4[lane + 32 * (8 * (bt + 1) + t)], pol);
        }
        #pragma unroll
        for (int t = 0; t < 8; ++t) {
            float4 v = sx4[lane + 32 * (8 * bt + t)];
            a0 = fmaf(buf[cur][t].x, v.x, a0);
            a1 = fmaf(buf[cur][t].y, v.y, a1);
            a2 = fmaf(buf[cur][t].z, v.z, a2);
            a3 = fmaf(buf[cur][t].w, v.w, a3);
        }
    }
    float acc = (a0 + a1) + (a2 + a3);

    #pragma unroll
    for (int off = 16; off; off >>= 1)
        acc += __shfl_xor_sync(0xFFFFFFFFu, acc, off);

    if (lane == 0) {
        float h = acc + b[row];
        if (ACT == 1)      h = tanhf(h);
        else if (ACT == 2) h = h - tanhf(h);
        y[row] = h;
    }
}

// ---------------------------------------------------------------------------
// pdist: out[i*1024 + j] = || a[i,:] - a[j,:] ||_2   (a: [1024, DIMS])
// ---------------------------------------------------------------------------
template<int DIMS>
__global__ void __launch_bounds__(256) pdist_kernel(const float* __restrict__ a,
                                                    float* __restrict__ out)
{
    __shared__ float s[NB * DIMS];
    for (int t = threadIdx.x; t < NB * DIMS; t += 256) s[t] = a[t];
    __syncthreads();

    const int idx = blockIdx.x * 256 + threadIdx.x;   // 0 .. 1024*1024-1
    const int i = idx >> 10;
    const int j = idx & (NB - 1);

    float d2 = 0.f;
    #pragma unroll
    for (int k = 0; k < DIMS; ++k) {
        float d = s[i * DIMS + k] - s[j * DIMS + k];
        d2 = fmaf(d, d, d2);
    }
    out[idx] = sqrtf(d2);
}

// ---------------------------------------------------------------------------
// kernel_launch: encoder (4 GEMV) -> pdists -> decoder (4 GEMV)
// L2 residency plan (126 MB L2): pin ew1 + ew2 + ew4 = 100.7 MB with
// evict_last policy; stream all other weights (176 MB) evict-first so they
// cannot displace the pinned set. Steady-state graph replays then source
// ~100 MB from L2 instead of DRAM.
// output layout: [output(3072) | in_diff(1024^2) | lat_diff(1024^2) | lat_repr(2048)]
// ---------------------------------------------------------------------------
extern "C" void kernel_launch(void* const* d_in, const int* in_sizes, int n_in,
                              void* d_out, int out_size)
{
    (void)in_sizes; (void)n_in; (void)out_size;

    const float* x   = (const float*)d_in[0];
    const float* ew1 = (const float*)d_in[1];
    const float* eb1 = (const float*)d_in[2];
    const float* ew2 = (const float*)d_in[3];
    const float* eb2 = (const float*)d_in[4];
    const float* ew3 = (const float*)d_in[5];
    const float* eb3 = (const float*)d_in[6];
    const float* ew4 = (const float*)d_in[7];
    const float* eb4 = (const float*)d_in[8];
    const float* dw1 = (const float*)d_in[9];
    const float* db1 = (const float*)d_in[10];
    const float* dw2 = (const float*)d_in[11];
    const float* db2 = (const float*)d_in[12];
    const float* dw3 = (const float*)d_in[13];
    const float* db3 = (const float*)d_in[14];
    const float* dw4 = (const float*)d_in[15];
    const float* db4 = (const float*)d_in[16];

    float* out      = (float*)d_out;
    float* out_main = out;                          // 3072
    float* out_ind  = out + AA;                     // 1024*1024
    float* out_lat  = out + AA + NB * NB;           // 1024*1024
    float* y        = out + AA + 2 * NB * NB;       // 2048 (lat_repr / encoder out)

    float *buf0, *buf1;
    cudaGetSymbolAddress((void**)&buf0, g_buf0);
    cudaGetSymbolAddress((void**)&buf1, g_buf1);

    // in_data pdist depends only on x — issue first
    pdist_kernel<3><<<(NB * NB) / 256, 256>>>(x, out_ind);

    // encoder (ew1, ew2 pinned; ew3 streamed; ew4 pinned)
    gemv_ws<1, AA, 1><<<AA / 8, 256>>>(ew1, x,    eb1, buf0);
    gemv_ws<1, AA, 1><<<AA / 8, 256>>>(ew2, buf0, eb2, buf1);
    gemv_ws<0, AA, 0><<<AA / 8, 256>>>(ew3, buf1, eb3, buf0);
    gemv_ws<2, AA, 1><<<DD / 8, 256>>>(ew4, buf0, eb4, y);    // tanhshrink

    // latent pdist
    pdist_kernel<2><<<(NB * NB) / 256, 256>>>(y, out_lat);

    // decoder (all streamed)
    gemv_ws<1, DD, 0><<<AA / 8, 256>>>(dw1, y,    db1, buf0);
    gemv_ws<1, AA, 0><<<AA / 8, 256>>>(dw2, buf0, db2, buf1);
    gemv_ws<0, AA, 0><<<AA / 8, 256>>>(dw3, buf1, db3, buf0);
    gemv_ws<1, AA, 0><<<AA / 8, 256>>>(dw4, buf0, db4, out_main);
}